// round 2
// baseline (speedup 1.0000x reference)
#include <cuda_runtime.h>
#include <cstdint>

// ProcessorNet: x[B,128]; 64 sequential steps:
//   reg = relu(x@wd.T + bd) * inst_t ; x += reg@wu.T + bu
// Reduced form (exact up to fp reassociation):
//   z_0 = x@wd.T + bd                          [B,16]
//   z_{t+1} = z_t + (relu(z_t)*inst_t)@A + c   A = wu.T@wd.T [16,16], c = bu@wd.T
//   out = x + (sum_t relu(z_t)*inst_t)@wu.T + 64*bu

#define HDIM 128
#define WDIM 16
#define LSTEPS 64

struct Consts {
    float2 A2[17][16];      // A2[j][i] splat; row 16 holds c (paired with r=1)
    float  prog[LSTEPS][16];
    float2 wd2[128][16];    // [h][i] = splat(wd[i*128+h])
    float2 wu2[128][16];    // [h][j] = splat(wu[h*16+j])
    float2 bd2[16];
    float2 bu2[128];        // splat(64*bu[h])
};

__device__ Consts g_c;

__global__ void setup_kernel(const float* __restrict__ prog,
                             const float* __restrict__ wd,
                             const float* __restrict__ bd,
                             const float* __restrict__ wu,
                             const float* __restrict__ bu) {
    int tid = threadIdx.x;  // 256 threads
    // A[j][i] = sum_h wu[h][j] * wd[i][h]
    {
        int j = tid >> 4, i = tid & 15;
        float s = 0.f;
        #pragma unroll 8
        for (int h = 0; h < HDIM; ++h) s += wu[h * WDIM + j] * wd[i * HDIM + h];
        g_c.A2[j][i] = make_float2(s, s);
    }
    if (tid < 16) {
        int i = tid;
        float s = 0.f;
        #pragma unroll 8
        for (int h = 0; h < HDIM; ++h) s += bu[h] * wd[i * HDIM + h];
        g_c.A2[16][i] = make_float2(s, s);   // c row
        float b = bd[i];
        g_c.bd2[i] = make_float2(b, b);
    }
    for (int idx = tid; idx < LSTEPS * 16; idx += 256)
        g_c.prog[idx >> 4][idx & 15] = prog[idx];
    for (int idx = tid; idx < 128 * 16; idx += 256) {
        int h = idx >> 4, i = idx & 15;
        float v = wd[i * HDIM + h];
        g_c.wd2[h][i] = make_float2(v, v);
        float u = wu[h * WDIM + i];
        g_c.wu2[h][i] = make_float2(u, u);
    }
    for (int idx = tid; idx < 128; idx += 256) {
        float v = 64.f * bu[idx];
        g_c.bu2[idx] = make_float2(v, v);
    }
}

// ---- packed f32x2 helpers (Blackwell fma.rn.f32x2 — 2x fp32 throughput) ----
typedef unsigned long long u64;

__device__ __forceinline__ u64 pk(float x, float y) {
    u64 r;
    asm("mov.b64 %0, {%1, %2};" : "=l"(r) : "f"(x), "f"(y));
    return r;
}
__device__ __forceinline__ void upk(u64 v, float& x, float& y) {
    asm("mov.b64 {%0, %1}, %2;" : "=f"(x), "=f"(y) : "l"(v));
}
__device__ __forceinline__ u64 f2u(float2 v) { return pk(v.x, v.y); }
__device__ __forceinline__ u64 fma2(u64 a, u64 b, u64 c) {
    u64 d;
    asm("fma.rn.f32x2 %0, %1, %2, %3;" : "=l"(d) : "l"(a), "l"(b), "l"(c));
    return d;
}
__device__ __forceinline__ u64 add2(u64 a, u64 b) {
    u64 d;
    asm("add.rn.f32x2 %0, %1, %2;" : "=l"(d) : "l"(a), "l"(b));
    return d;
}

__global__ __launch_bounds__(256)
void proc_kernel(const float* __restrict__ x, float* __restrict__ out) {
    __shared__ Consts s;
    {   // cooperative copy of constants into shared
        const float4* src = (const float4*)&g_c;
        float4* dst = (float4*)&s;
        const int n = (int)(sizeof(Consts) / 16);
        for (int i = threadIdx.x; i < n; i += 256) dst[i] = src[i];
    }
    __syncthreads();

    size_t pair = (size_t)blockIdx.x * 256 + threadIdx.x;  // 2 rows per thread
    const float* x0 = x + pair * 2 * HDIM;
    const float* x1 = x0 + HDIM;
    float* o0 = out + pair * 2 * HDIM;
    float* o1 = o0 + HDIM;

    u64 z[16], R[16];
    #pragma unroll
    for (int i = 0; i < 16; i++) { z[i] = f2u(s.bd2[i]); R[i] = 0ull; }

    // ---- phase A: z = x @ wd.T + bd ----
    #pragma unroll 2
    for (int h = 0; h < HDIM; h += 4) {
        float4 a0 = *(const float4*)(x0 + h);
        float4 a1 = *(const float4*)(x1 + h);
        float av0[4] = {a0.x, a0.y, a0.z, a0.w};
        float av1[4] = {a1.x, a1.y, a1.z, a1.w};
        #pragma unroll
        for (int k = 0; k < 4; k++) {
            u64 xv = pk(av0[k], av1[k]);
            const ulonglong2* wrow = (const ulonglong2*)&s.wd2[h + k][0];
            #pragma unroll
            for (int i = 0; i < 16; i += 2) {
                ulonglong2 w = wrow[i >> 1];
                z[i]     = fma2(xv, w.x, z[i]);
                z[i + 1] = fma2(xv, w.y, z[i + 1]);
            }
        }
    }

    // ---- phase B: 64-step recurrence in 16-dim space ----
    const u64 one2 = pk(1.f, 1.f);
    #pragma unroll 1
    for (int t = 0; t < LSTEPS; t++) {
        u64 r[16];
        #pragma unroll
        for (int j = 0; j < 16; j++) {
            float zx, zy;
            upk(z[j], zx, zy);
            float p = s.prog[t][j];
            float rx = fmaxf(zx, 0.f) * p;
            float ry = fmaxf(zy, 0.f) * p;
            r[j] = pk(rx, ry);
            R[j] = add2(R[j], r[j]);
        }
        #pragma unroll
        for (int j = 0; j < 17; j++) {
            u64 rj = (j < 16) ? r[j] : one2;   // row 16 of A is c, paired with 1.0
            const ulonglong2* arow = (const ulonglong2*)&s.A2[j][0];
            #pragma unroll
            for (int i = 0; i < 16; i += 2) {
                ulonglong2 a = arow[i >> 1];
                z[i]     = fma2(rj, a.x, z[i]);
                z[i + 1] = fma2(rj, a.y, z[i + 1]);
            }
        }
    }

    // ---- phase C: out = x + R @ wu.T + 64*bu ----
    #pragma unroll 2
    for (int h = 0; h < HDIM; h += 4) {
        float4 a0 = *(const float4*)(x0 + h);
        float4 a1 = *(const float4*)(x1 + h);
        float av0[4] = {a0.x, a0.y, a0.z, a0.w};
        float av1[4] = {a1.x, a1.y, a1.z, a1.w};
        float b0[4], b1[4];
        #pragma unroll
        for (int k = 0; k < 4; k++) {
            u64 acc = add2(pk(av0[k], av1[k]), f2u(s.bu2[h + k]));
            const ulonglong2* urow = (const ulonglong2*)&s.wu2[h + k][0];
            #pragma unroll
            for (int j = 0; j < 16; j += 2) {
                ulonglong2 u = urow[j >> 1];
                acc = fma2(R[j], u.x, acc);
                acc = fma2(R[j + 1], u.y, acc);
            }
            float ox, oy;
            upk(acc, ox, oy);
            b0[k] = ox;
            b1[k] = oy;
        }
        *(float4*)(o0 + h) = make_float4(b0[0], b0[1], b0[2], b0[3]);
        *(float4*)(o1 + h) = make_float4(b1[0], b1[1], b1[2], b1[3]);
    }
}

extern "C" void kernel_launch(void* const* d_in, const int* in_sizes, int n_in,
                              void* d_out, int out_size) {
    const float* x    = (const float*)d_in[0];
    const float* prog = (const float*)d_in[1];
    const float* wd   = (const float*)d_in[2];
    const float* bd   = (const float*)d_in[3];
    const float* wu   = (const float*)d_in[4];
    const float* bu   = (const float*)d_in[5];
    float* out = (float*)d_out;

    setup_kernel<<<1, 256>>>(prog, wd, bd, wu, bu);

    // B = 262144 rows, 2 rows/thread, 256 threads/block -> 512 blocks
    int pairs = (in_sizes[0] / HDIM) / 2;
    int blocks = (pairs + 255) / 256;
    proc_kernel<<<blocks, 256>>>(x, out);
}

// round 3
// speedup vs baseline: 3.2389x; 3.2389x over previous
#include <cuda_runtime.h>
#include <cstdint>

// ProcessorNet reduction (exact up to fp reassociation):
//   z_0 = x@wd.T + bd                              [B,16]
//   z_{t+1} = z_t + relu(z_t) @ P_t + c,  P_t = diag(prog_t) @ A,  A = wu.T@wd.T
//   R = sum_t relu(z_t)*prog_t ;  out = x + R@wu.T + 64*bu
//
// One row per thread; z packed column-wise as 8x f32x2 (fma.rn.f32x2).

#define HDIM 128
#define LSTEPS 64

struct Consts {
    float P[LSTEPS][16][16];   // 64KB: P[t][j][i] = prog[t][j]*A[j][i]
    float wd2[128][16];        // wd2[h][i] = wd[i][h]
    float prog[LSTEPS][16];
    float wupc[64][16][2];     // wupc[hp][j] = {wu[2hp][j], wu[2hp+1][j]}
    float c2[16];              // c[i] = sum_h bu[h]*wd[i][h]
    float bd[16];
    float bu64[128];           // 64*bu[h]
    float A[16][16];           // scratch (not copied to smem)
};
__device__ Consts g_c;

// persistent consts (everything between wd2 and bu64 inclusive)
#define PERSIST_FLOATS (2048 + 1024 + 2048 + 16 + 16 + 128)   // 5280
#define SMEM_FLOATS (16384 + PERSIST_FLOATS)                   // 21664
#define SMEM_BYTES (SMEM_FLOATS * 4)                           // 86656

__global__ void setup_kernel(const float* __restrict__ prog,
                             const float* __restrict__ wd,
                             const float* __restrict__ bd,
                             const float* __restrict__ wu,
                             const float* __restrict__ bu) {
    int tid = threadIdx.x;  // 256 threads, 1 block
    {   // A[j][i] = sum_h wu[h][j] * wd[i][h]
        int j = tid >> 4, i = tid & 15;
        float s = 0.f;
        #pragma unroll 8
        for (int h = 0; h < HDIM; ++h) s += wu[h * 16 + j] * wd[i * HDIM + h];
        g_c.A[j][i] = s;
    }
    if (tid < 16) {
        int i = tid;
        float s = 0.f;
        #pragma unroll 8
        for (int h = 0; h < HDIM; ++h) s += bu[h] * wd[i * HDIM + h];
        g_c.c2[i] = s;
        g_c.bd[i] = bd[i];
    }
    for (int idx = tid; idx < LSTEPS * 16; idx += 256)
        g_c.prog[idx >> 4][idx & 15] = prog[idx];
    for (int idx = tid; idx < 128 * 16; idx += 256) {
        int h = idx >> 4, i = idx & 15;
        g_c.wd2[h][i] = wd[i * HDIM + h];
    }
    for (int idx = tid; idx < 64 * 16; idx += 256) {
        int hp = idx >> 4, j = idx & 15;
        g_c.wupc[hp][j][0] = wu[(2 * hp) * 16 + j];
        g_c.wupc[hp][j][1] = wu[(2 * hp + 1) * 16 + j];
    }
    for (int idx = tid; idx < 128; idx += 256) g_c.bu64[idx] = 64.f * bu[idx];
    __syncthreads();
    for (int idx = tid; idx < LSTEPS * 256; idx += 256) {
        int t = idx >> 8, j = (idx >> 4) & 15, i = idx & 15;
        g_c.P[t][j][i] = g_c.prog[t][j] * g_c.A[j][i];
    }
}

// ---- packed f32x2 helpers ----
typedef unsigned long long u64;

__device__ __forceinline__ u64 pk(float x, float y) {
    u64 r; asm("mov.b64 %0, {%1, %2};" : "=l"(r) : "f"(x), "f"(y)); return r;
}
__device__ __forceinline__ void upk(u64 v, float& x, float& y) {
    asm("mov.b64 {%0, %1}, %2;" : "=f"(x), "=f"(y) : "l"(v));
}
__device__ __forceinline__ u64 fma2(u64 a, u64 b, u64 c) {
    u64 d; asm("fma.rn.f32x2 %0, %1, %2, %3;" : "=l"(d) : "l"(a), "l"(b), "l"(c)); return d;
}
__device__ __forceinline__ u64 add2(u64 a, u64 b) {
    u64 d; asm("add.rn.f32x2 %0, %1, %2;" : "=l"(d) : "l"(a), "l"(b)); return d;
}

__global__ __launch_bounds__(256)
void proc_kernel(const float* __restrict__ x, float* __restrict__ out) {
    extern __shared__ float sm[];
    float* tile   = sm;                    // 16384 floats, aliases P region
    float* s_wd2  = sm + 16384;            // 2048
    float* s_prog = s_wd2 + 2048;          // 1024
    float* s_wupc = s_prog + 1024;         // 2048
    float* s_c2   = s_wupc + 2048;         // 16
    float* s_bd   = s_c2 + 16;             // 16
    float* s_bu   = s_bd + 16;             // 128

    int tid = threadIdx.x;

    // copy persistent consts (wd2..bu64 are contiguous in Consts)
    {
        const float4* src = (const float4*)&g_c.wd2[0][0];
        float4* dst = (float4*)(sm + 16384);
        for (int i = tid; i < PERSIST_FLOATS / 4; i += 256) dst[i] = src[i];
    }
    __syncthreads();

    long row0 = (long)blockIdx.x * 256;
    const float* xr = x + row0 * HDIM;
    float* outr = out + row0 * HDIM;

    u64 z2[8];
    #pragma unroll
    for (int k = 0; k < 8; ++k) z2[k] = pk(s_bd[2 * k], s_bd[2 * k + 1]);

    // ---- phase A: z = x @ wd.T + bd (x staged via coalesced smem tile) ----
    for (int ch = 0; ch < 4; ++ch) {
        __syncthreads();
        for (int f = tid; f < 8192; f += 256) {
            int r = f >> 5, c = f & 31;
            tile[r * 33 + c] = xr[(long)r * HDIM + ch * 32 + c];
        }
        __syncthreads();
        #pragma unroll
        for (int c = 0; c < 32; ++c) {
            float xv = tile[tid * 33 + c];
            u64 xs = pk(xv, xv);
            const u64* w = (const u64*)(s_wd2 + (ch * 32 + c) * 16);
            #pragma unroll
            for (int k = 0; k < 8; ++k) z2[k] = fma2(xs, w[k], z2[k]);
        }
    }

    // ---- load P into smem (tile region reused) ----
    __syncthreads();
    {
        const float4* src = (const float4*)&g_c.P[0][0][0];
        float4* dst = (float4*)sm;
        for (int i = tid; i < 4096; i += 256) dst[i] = src[i];
    }
    __syncthreads();

    // ---- phase B: 64-step recurrence ----
    float Racc[16];
    #pragma unroll
    for (int j = 0; j < 16; ++j) Racc[j] = 0.f;
    u64 c2r[8];
    #pragma unroll
    for (int k = 0; k < 8; ++k) c2r[k] = pk(s_c2[2 * k], s_c2[2 * k + 1]);

    #pragma unroll 1
    for (int t = 0; t < LSTEPS; ++t) {
        float m[16];
        #pragma unroll
        for (int k = 0; k < 8; ++k) upk(z2[k], m[2 * k], m[2 * k + 1]);
        #pragma unroll
        for (int j = 0; j < 16; ++j) m[j] = fmaxf(m[j], 0.f);
        const float* pr = s_prog + t * 16;
        #pragma unroll
        for (int j = 0; j < 16; ++j) Racc[j] = fmaf(m[j], pr[j], Racc[j]);
        const u64* Pt = (const u64*)(sm + t * 256);
        #pragma unroll
        for (int j = 0; j < 16; ++j) {
            u64 mj = pk(m[j], m[j]);
            const u64* Prow = Pt + j * 8;
            #pragma unroll
            for (int k = 0; k < 8; ++k) z2[k] = fma2(mj, Prow[k], z2[k]);
        }
        #pragma unroll
        for (int k = 0; k < 8; ++k) z2[k] = add2(z2[k], c2r[k]);
    }

    // ---- phase C: out = x + R @ wu.T + 64*bu (staged through tile) ----
    u64 Rs[16];
    #pragma unroll
    for (int j = 0; j < 16; ++j) Rs[j] = pk(Racc[j], Racc[j]);

    for (int ch = 0; ch < 4; ++ch) {
        __syncthreads();
        #pragma unroll
        for (int hp = 0; hp < 16; ++hp) {
            int h2 = ch * 16 + hp;
            const u64* wu = (const u64*)(s_wupc + h2 * 32);
            u64 acc = *(const u64*)(s_bu + h2 * 2);
            #pragma unroll
            for (int j = 0; j < 16; ++j) acc = fma2(Rs[j], wu[j], acc);
            float y0, y1;
            upk(acc, y0, y1);
            tile[tid * 33 + 2 * hp]     = y0;
            tile[tid * 33 + 2 * hp + 1] = y1;
        }
        __syncthreads();
        for (int f = tid; f < 8192; f += 256) {
            int r = f >> 5, c = f & 31;
            long g = (long)r * HDIM + ch * 32 + c;
            outr[g] = xr[g] + tile[r * 33 + c];
        }
    }
}

extern "C" void kernel_launch(void* const* d_in, const int* in_sizes, int n_in,
                              void* d_out, int out_size) {
    const float* x    = (const float*)d_in[0];
    const float* prog = (const float*)d_in[1];
    const float* wd   = (const float*)d_in[2];
    const float* bd   = (const float*)d_in[3];
    const float* wu   = (const float*)d_in[4];
    const float* bu   = (const float*)d_in[5];
    float* out = (float*)d_out;

    cudaFuncSetAttribute(proc_kernel,
                         cudaFuncAttributeMaxDynamicSharedMemorySize, SMEM_BYTES);

    setup_kernel<<<1, 256>>>(prog, wd, bd, wu, bu);

    int rows = in_sizes[0] / HDIM;          // 262144
    int blocks = rows / 256;                // 1024
    proc_kernel<<<blocks, 256, SMEM_BYTES>>>(x, out);
}

// round 4
// speedup vs baseline: 5.4407x; 1.6798x over previous
#include <cuda_runtime.h>
#include <cstdint>

// ProcessorNet reduction (exact up to fp reassociation):
//   z_0 = x@wd.T + bd                              [B,16]
//   z_{t+1} = z_t + relu(z_t) @ P_t + c,  P_t = diag(prog_t) @ A,  A = wu.T@wd.T
//   R = sum_t relu(z_t)*prog_t ;  out = x + R@wu.T + 64*bu
// One row per thread; z packed column-wise as 8x f32x2 (fma.rn.f32x2).
// P has a 17th row per step holding c (multiplied by splat 1.0).

#define HDIM 128
#define LSTEPS 64

struct Consts {
    float Pc[LSTEPS][17][16];  // Pc[t][j][i]=prog[t][j]*A[j][i]; row16 = c
    float wd2[128][16];        // wd2[h][i] = wd[i][h]
    float prog[LSTEPS][16];
    float wupc[64][16][2];     // wupc[hp][j] = {wu[2hp][j], wu[2hp+1][j]}
    float bd[16];
    float bu64[128];           // 64*bu[h]
    float A[16][16];           // scratch
    float c[16];               // scratch
};
__device__ Consts g_c;

// shared layout (floats):
//   region0: max(tile 256*33=8448, Pbuf 32*17*16=8704) = 8704
//   persist: wd2 2048 + prog 1024 + wupc 2048 + bd 16 + bu64 128 = 5264
#define REGION0_FLOATS 8704
#define PERSIST_FLOATS 5264
#define SMEM_FLOATS (REGION0_FLOATS + PERSIST_FLOATS)  // 13968
#define SMEM_BYTES (SMEM_FLOATS * 4)                   // 55872

__global__ void setup_kernel(const float* __restrict__ prog,
                             const float* __restrict__ wd,
                             const float* __restrict__ bd,
                             const float* __restrict__ wu,
                             const float* __restrict__ bu) {
    int tid = threadIdx.x;  // 256 threads, 1 block
    {   // A[j][i] = sum_h wu[h][j] * wd[i][h]
        int j = tid >> 4, i = tid & 15;
        float s = 0.f;
        #pragma unroll 8
        for (int h = 0; h < HDIM; ++h) s += wu[h * 16 + j] * wd[i * HDIM + h];
        g_c.A[j][i] = s;
    }
    if (tid < 16) {
        int i = tid;
        float s = 0.f;
        #pragma unroll 8
        for (int h = 0; h < HDIM; ++h) s += bu[h] * wd[i * HDIM + h];
        g_c.c[i] = s;
        g_c.bd[i] = bd[i];
    }
    for (int idx = tid; idx < LSTEPS * 16; idx += 256)
        g_c.prog[idx >> 4][idx & 15] = prog[idx];
    for (int idx = tid; idx < 128 * 16; idx += 256) {
        int h = idx >> 4, i = idx & 15;
        g_c.wd2[h][i] = wd[i * HDIM + h];
    }
    for (int idx = tid; idx < 64 * 16; idx += 256) {
        int hp = idx >> 4, j = idx & 15;
        g_c.wupc[hp][j][0] = wu[(2 * hp) * 16 + j];
        g_c.wupc[hp][j][1] = wu[(2 * hp + 1) * 16 + j];
    }
    for (int idx = tid; idx < 128; idx += 256) g_c.bu64[idx] = 64.f * bu[idx];
    __syncthreads();
    for (int idx = tid; idx < LSTEPS * 17 * 16; idx += 256) {
        int t = idx / 272, rem = idx % 272;
        int j = rem >> 4, i = rem & 15;
        g_c.Pc[t][j][i] = (j < 16) ? g_c.prog[t][j] * g_c.A[j][i] : g_c.c[i];
    }
}

// ---- packed f32x2 helpers ----
typedef unsigned long long u64;

__device__ __forceinline__ u64 pk(float x, float y) {
    u64 r; asm("mov.b64 %0, {%1, %2};" : "=l"(r) : "f"(x), "f"(y)); return r;
}
__device__ __forceinline__ void upk(u64 v, float& x, float& y) {
    asm("mov.b64 {%0, %1}, %2;" : "=f"(x), "=f"(y) : "l"(v));
}
__device__ __forceinline__ u64 fma2(u64 a, u64 b, u64 c) {
    u64 d; asm("fma.rn.f32x2 %0, %1, %2, %3;" : "=l"(d) : "l"(a), "l"(b), "l"(c)); return d;
}

__global__ __launch_bounds__(256, 3)
void proc_kernel(const float* __restrict__ x, float* __restrict__ out) {
    extern __shared__ float sm[];
    float* region0 = sm;                      // tile (phases A/C) | Pbuf (phase B)
    float* s_wd2   = sm + REGION0_FLOATS;     // 2048
    float* s_prog  = s_wd2 + 2048;            // 1024
    float* s_wupc  = s_prog + 1024;           // 2048
    float* s_bd    = s_wupc + 2048;           // 16
    float* s_bu    = s_bd + 16;               // 128

    int tid = threadIdx.x;

    // copy persistent consts (wd2..bu64 contiguous in Consts)
    {
        const float4* src = (const float4*)&g_c.wd2[0][0];
        float4* dst = (float4*)(sm + REGION0_FLOATS);
        for (int i = tid; i < PERSIST_FLOATS / 4; i += 256) dst[i] = src[i];
    }
    __syncthreads();

    long row0 = (long)blockIdx.x * 256;
    const float* xr = x + row0 * HDIM;
    float* outr = out + row0 * HDIM;

    u64 z2[8];
    #pragma unroll
    for (int k = 0; k < 8; ++k) z2[k] = *(const u64*)(s_bd + 2 * k);

    // ---- phase A: z = x @ wd.T + bd (x staged via coalesced smem tile) ----
    for (int ch = 0; ch < 4; ++ch) {
        __syncthreads();
        for (int f = tid; f < 8192; f += 256) {
            int r = f >> 5, c = f & 31;
            region0[r * 33 + c] = xr[(long)r * HDIM + ch * 32 + c];
        }
        __syncthreads();
        #pragma unroll
        for (int c = 0; c < 32; ++c) {
            float xv = region0[tid * 33 + c];
            u64 xs = pk(xv, xv);
            const ulonglong2* w = (const ulonglong2*)(s_wd2 + (ch * 32 + c) * 16);
            #pragma unroll
            for (int kk = 0; kk < 4; ++kk) {
                ulonglong2 wv = w[kk];
                z2[2 * kk]     = fma2(xs, wv.x, z2[2 * kk]);
                z2[2 * kk + 1] = fma2(xs, wv.y, z2[2 * kk + 1]);
            }
        }
    }

    // ---- phase B: 64-step recurrence, P staged in two 32-step chunks ----
    u64 Racc2[8];
    #pragma unroll
    for (int k = 0; k < 8; ++k) Racc2[k] = 0ull;
    const u64 one2 = pk(1.f, 1.f);

    for (int chunk = 0; chunk < 2; ++chunk) {
        __syncthreads();
        {
            const float4* src = (const float4*)&g_c.Pc[chunk * 32][0][0];
            float4* dst = (float4*)region0;
            for (int i = tid; i < (32 * 17 * 16) / 4; i += 256) dst[i] = src[i];
        }
        __syncthreads();

        #pragma unroll 1
        for (int tt = 0; tt < 32; ++tt) {
            int t = chunk * 32 + tt;
            float m[16];
            #pragma unroll
            for (int k = 0; k < 8; ++k) upk(z2[k], m[2 * k], m[2 * k + 1]);
            #pragma unroll
            for (int j = 0; j < 16; ++j) m[j] = fmaxf(m[j], 0.f);

            const u64* pr2 = (const u64*)(s_prog + t * 16);
            #pragma unroll
            for (int k = 0; k < 8; ++k)
                Racc2[k] = fma2(pk(m[2 * k], m[2 * k + 1]), pr2[k], Racc2[k]);

            const float* Pt = region0 + tt * 272;
            #pragma unroll
            for (int j = 0; j < 17; ++j) {
                u64 mj = (j < 16) ? pk(m[j], m[j]) : one2;
                const ulonglong2* prow = (const ulonglong2*)(Pt + j * 16);
                #pragma unroll
                for (int kk = 0; kk < 4; ++kk) {
                    ulonglong2 p = prow[kk];
                    z2[2 * kk]     = fma2(mj, p.x, z2[2 * kk]);
                    z2[2 * kk + 1] = fma2(mj, p.y, z2[2 * kk + 1]);
                }
            }
        }
    }

    // ---- phase C: out = x + R @ wu.T + 64*bu (staged through tile) ----
    u64 Rs[16];
    #pragma unroll
    for (int k = 0; k < 8; ++k) {
        float r0, r1;
        upk(Racc2[k], r0, r1);
        Rs[2 * k]     = pk(r0, r0);
        Rs[2 * k + 1] = pk(r1, r1);
    }

    for (int ch = 0; ch < 4; ++ch) {
        __syncthreads();
        #pragma unroll
        for (int hp = 0; hp < 16; ++hp) {
            int h2 = ch * 16 + hp;
            u64 acc = *(const u64*)(s_bu + h2 * 2);
            const ulonglong2* urow = (const ulonglong2*)(s_wupc + h2 * 32);
            #pragma unroll
            for (int jj = 0; jj < 8; ++jj) {
                ulonglong2 u = urow[jj];
                acc = fma2(Rs[2 * jj],     u.x, acc);
                acc = fma2(Rs[2 * jj + 1], u.y, acc);
            }
            float y0, y1;
            upk(acc, y0, y1);
            region0[tid * 33 + 2 * hp]     = y0;
            region0[tid * 33 + 2 * hp + 1] = y1;
        }
        __syncthreads();
        for (int f = tid; f < 8192; f += 256) {
            int r = f >> 5, c = f & 31;
            long g = (long)r * HDIM + ch * 32 + c;
            outr[g] = xr[g] + region0[r * 33 + c];
        }
    }
}

extern "C" void kernel_launch(void* const* d_in, const int* in_sizes, int n_in,
                              void* d_out, int out_size) {
    const float* x    = (const float*)d_in[0];
    const float* prog = (const float*)d_in[1];
    const float* wd   = (const float*)d_in[2];
    const float* bd   = (const float*)d_in[3];
    const float* wu   = (const float*)d_in[4];
    const float* bu   = (const float*)d_in[5];
    float* out = (float*)d_out;

    cudaFuncSetAttribute(proc_kernel,
                         cudaFuncAttributeMaxDynamicSharedMemorySize, SMEM_BYTES);

    setup_kernel<<<1, 256>>>(prog, wd, bd, wu, bu);

    int rows = in_sizes[0] / HDIM;          // 262144
    int blocks = rows / 256;                // 1024
    proc_kernel<<<blocks, 256, SMEM_BYTES>>>(x, out);
}